// round 1
// baseline (speedup 1.0000x reference)
#include <cuda_runtime.h>

#define K_RINGS 192
#define PMAX    404
#define MDIM    192
#define LDIM    192
#define BC      1024
#define NGRID   41088
#define TWO_PI_F 6.2831853071795864769f
#define XS_STRIDE 408   // 404 padded to /4 and bank-friendly

// Intermediate DFT results, layout [m][k][bc] (bc contiguous)
__device__ float g_re[(size_t)MDIM * K_RINGS * BC];
__device__ float g_im[(size_t)MDIM * K_RINGS * BC];

__device__ __forceinline__ unsigned long long pk2(float lo, float hi) {
    unsigned long long r;
    asm("mov.b64 %0,{%1,%2};" : "=l"(r) : "f"(lo), "f"(hi));
    return r;
}
__device__ __forceinline__ void upk2(unsigned long long v, float& lo, float& hi) {
    asm("mov.b64 {%0,%1},%2;" : "=f"(lo), "=f"(hi) : "l"(v));
}
__device__ __forceinline__ unsigned long long ffma2(unsigned long long a,
                                                    unsigned long long b,
                                                    unsigned long long c) {
    unsigned long long d;
    asm("fma.rn.f32x2 %0,%1,%2,%3;" : "=l"(d) : "l"(a), "l"(b), "l"(c));
    return d;
}

// ---------------------------------------------------------------------------
// Stage A: ragged per-ring real DFT.
// grid = (K=192, BC/32, 4 m-tiles of 48), block = (12, 16) = 192 threads.
// Thread (tx,ty): m = mz*48 + 4*tx .. +3 (float4 basis loads), rows ty, ty+16.
// ---------------------------------------------------------------------------
extern "C" __global__ void __launch_bounds__(192)
sht_stageA(const float* __restrict__ x,
           const float* __restrict__ cosb,
           const float* __restrict__ sinb,
           const int*   __restrict__ ring_idx)
{
    extern __shared__ float xs[];   // 32 rows x XS_STRIDE
    const int k   = blockIdx.x;
    const int bc0 = blockIdx.y * 32;
    const int mz  = blockIdx.z;     // m tile index (48 wide)
    const int tx  = threadIdx.x;    // 0..11
    const int ty  = threadIdx.y;    // 0..15
    const int t   = ty * 12 + tx;

    const int slon = ring_idx[k * PMAX];
    const int nlon = ring_idx[k * PMAX + PMAX - 1] - slon + 1;
    const int mmax = min(MDIM - 1, nlon >> 1);

    if (mz * 48 > mmax) {
        // whole m-tile masked: write zeros into the intermediate
        for (int idx = t; idx < 48 * 32; idx += 192) {
            int ml = idx >> 5, bcl = idx & 31;
            size_t o = ((size_t)(mz * 48 + ml) * K_RINGS + k) * BC + bc0 + bcl;
            g_re[o] = 0.f; g_im[o] = 0.f;
        }
        return;
    }

    // Load 32 x-rows for this ring into shared memory (vectorized, contiguous)
    {
        int r  = t >> 6;          // 0..2
        int pc = (t & 63) * 4;
        for (; r < 32; r += 3) {
            const float* xr = x + (size_t)(bc0 + r) * NGRID + slon;
            for (int p = pc; p < nlon; p += 256)
                *(float4*)&xs[r * XS_STRIDE + p] = *(const float4*)&xr[p];
        }
    }
    __syncthreads();

    const int m0 = mz * 48 + tx * 4;
    const float* cb = cosb + (size_t)k * PMAX * MDIM + m0;
    const float* sb = sinb + (size_t)k * PMAX * MDIM + m0;

    unsigned long long acc[2][4];
#pragma unroll
    for (int i = 0; i < 2; i++)
#pragma unroll
        for (int j = 0; j < 4; j++) acc[i][j] = 0ull;

    const float* xr0 = xs + ty * XS_STRIDE;
    const float* xr1 = xs + (ty + 16) * XS_STRIDE;

#pragma unroll 2
    for (int p = 0; p < nlon; ++p) {
        float4 c4 = *(const float4*)(cb + (size_t)p * MDIM);
        float4 s4 = *(const float4*)(sb + (size_t)p * MDIM);
        unsigned long long b0 = pk2(c4.x, s4.x);
        unsigned long long b1 = pk2(c4.y, s4.y);
        unsigned long long b2 = pk2(c4.z, s4.z);
        unsigned long long b3 = pk2(c4.w, s4.w);
        float v0 = xr0[p], v1 = xr1[p];
        unsigned long long vv0 = pk2(v0, v0);
        unsigned long long vv1 = pk2(v1, v1);
        acc[0][0] = ffma2(b0, vv0, acc[0][0]);
        acc[0][1] = ffma2(b1, vv0, acc[0][1]);
        acc[0][2] = ffma2(b2, vv0, acc[0][2]);
        acc[0][3] = ffma2(b3, vv0, acc[0][3]);
        acc[1][0] = ffma2(b0, vv1, acc[1][0]);
        acc[1][1] = ffma2(b1, vv1, acc[1][1]);
        acc[1][2] = ffma2(b2, vv1, acc[1][2]);
        acc[1][3] = ffma2(b3, vv1, acc[1][3]);
    }
    __syncthreads();   // done with xs as x-tile; reuse for transpose staging

    float* s_re = xs;               // [48][33]
    float* s_im = xs + 48 * 33;
#pragma unroll
    for (int i = 0; i < 2; i++) {
        int bcl = ty + 16 * i;
#pragma unroll
        for (int j = 0; j < 4; j++) {
            float re, im; upk2(acc[i][j], re, im);
            int ml = tx * 4 + j;
            s_re[ml * 33 + bcl] = re * TWO_PI_F;
            s_im[ml * 33 + bcl] = im * TWO_PI_F;
        }
    }
    __syncthreads();
    for (int idx = t; idx < 48 * 32; idx += 192) {
        int ml = idx >> 5, bcl = idx & 31;
        size_t o = ((size_t)(mz * 48 + ml) * K_RINGS + k) * BC + bc0 + bcl;
        g_re[o] = s_re[ml * 33 + bcl];
        g_im[o] = s_im[ml * 33 + bcl];
    }
}

// ---------------------------------------------------------------------------
// Stage B: per-m GEMM over latitudes: out[bc,l,m] = sum_k A[m,k,bc]*W[m,l,k].
// grid = (BC/64, LDIM/64, MDIM), block = (16,16); 4x4 micro-tile of float2.
// Triangle: weight[m,l,k]==0 for l<m -> skip fully-below tiles (write zeros).
// ---------------------------------------------------------------------------
extern "C" __global__ void __launch_bounds__(256)
sht_stageB(const float* __restrict__ weight, float2* __restrict__ out)
{
    const int m   = blockIdx.z;
    const int bc0 = blockIdx.x * 64;
    const int l0  = blockIdx.y * 64;
    const int txx = threadIdx.x;   // 0..15 -> bc
    const int tyy = threadIdx.y;   // 0..15 -> l
    const int t   = tyy * 16 + txx;

    if (l0 + 63 < m) {             // entire tile is l<m: zeros
#pragma unroll
        for (int j = 0; j < 4; j++)
#pragma unroll
            for (int i = 0; i < 4; i++) {
                int bc = bc0 + txx + 16 * i;
                int l  = l0 + tyy + 16 * j;
                out[((size_t)bc * LDIM + l) * MDIM + m] = make_float2(0.f, 0.f);
            }
        return;
    }

    __shared__ float2 sA[16][64];   // [k][bc] interleaved (re,im)
    __shared__ float  sW[64][17];   // [l][k], padded

    unsigned long long acc[4][4];
#pragma unroll
    for (int j = 0; j < 4; j++)
#pragma unroll
        for (int i = 0; i < 4; i++) acc[j][i] = 0ull;

    for (int kb = 0; kb < K_RINGS; kb += 16) {
#pragma unroll
        for (int r = 0; r < 4; ++r) {
            int idx = t + r * 256;            // 0..1023
            int kk = idx >> 6, bcl = idx & 63;
            size_t o = ((size_t)m * K_RINGS + kb + kk) * BC + bc0 + bcl;
            sA[kk][bcl] = make_float2(g_re[o], g_im[o]);
        }
#pragma unroll
        for (int r = 0; r < 4; ++r) {
            int idx = t + r * 256;
            int ll = idx >> 4, kk = idx & 15;
            sW[ll][kk] = weight[((size_t)m * LDIM + l0 + ll) * K_RINGS + kb + kk];
        }
        __syncthreads();
#pragma unroll
        for (int kk = 0; kk < 16; ++kk) {
            unsigned long long a[4];
#pragma unroll
            for (int i = 0; i < 4; i++)
                a[i] = *(const unsigned long long*)&sA[kk][txx + 16 * i];
#pragma unroll
            for (int j = 0; j < 4; j++) {
                float w = sW[tyy + 16 * j][kk];
                unsigned long long wv = pk2(w, w);
#pragma unroll
                for (int i = 0; i < 4; i++)
                    acc[j][i] = ffma2(a[i], wv, acc[j][i]);
            }
        }
        __syncthreads();
    }

#pragma unroll
    for (int j = 0; j < 4; j++)
#pragma unroll
        for (int i = 0; i < 4; i++) {
            int bc = bc0 + txx + 16 * i;
            int l  = l0 + tyy + 16 * j;
            float re, im; upk2(acc[j][i], re, im);
            out[((size_t)bc * LDIM + l) * MDIM + m] = make_float2(re, im);
        }
}

// ---------------------------------------------------------------------------

extern "C" void kernel_launch(void* const* d_in, const int* in_sizes, int n_in,
                              void* d_out, int out_size)
{
    (void)in_sizes; (void)n_in; (void)out_size;
    const float* x        = (const float*)d_in[0];
    const float* weight   = (const float*)d_in[1];
    const float* cosb     = (const float*)d_in[2];
    const float* sinb     = (const float*)d_in[3];
    const int*   ring_idx = (const int*)d_in[4];

    const int smemA = 32 * XS_STRIDE * sizeof(float);   // 52224 B
    cudaFuncSetAttribute(sht_stageA, cudaFuncAttributeMaxDynamicSharedMemorySize, smemA);

    dim3 gA(K_RINGS, BC / 32, 4), bA(12, 16);
    sht_stageA<<<gA, bA, smemA>>>(x, cosb, sinb, ring_idx);

    dim3 gB(BC / 64, LDIM / 64, MDIM), bB(16, 16);
    sht_stageB<<<gB, bB>>>(weight, (float2*)d_out);
}

// round 2
// speedup vs baseline: 1.5866x; 1.5866x over previous
#include <cuda_runtime.h>

#define NGRID   41088
#define PMAX    404
#define MDIM    192
#define KR      192
#define BCN     1024
#define TWO_PI_F 6.28318530717958647692f

typedef unsigned long long u64;
typedef unsigned int u32;

// Intermediate (re,im) pairs, layout [m][k][bc]
__device__ float2 g_ri[(size_t)MDIM * KR * BCN];

__device__ __forceinline__ u64 ffma2(u64 a, u64 b, u64 c) {
    u64 d; asm("fma.rn.f32x2 %0,%1,%2,%3;" : "=l"(d) : "l"(a), "l"(b), "l"(c)); return d;
}
__device__ __forceinline__ u64 fmul2(u64 a, u64 b) {
    u64 d; asm("mul.rn.f32x2 %0,%1,%2;" : "=l"(d) : "l"(a), "l"(b)); return d;
}
__device__ __forceinline__ u64 pk2(float lo, float hi) {
    u64 r; asm("mov.b64 %0,{%1,%2};" : "=l"(r) : "f"(lo), "f"(hi)); return r;
}
__device__ __forceinline__ void lds2(u64& a, u64& b, u32 addr) {
    asm volatile("ld.shared.v2.u64 {%0,%1},[%2];" : "=l"(a), "=l"(b) : "r"(addr));
}
__device__ __forceinline__ void sts4(u32 addr, float a, float b, float c, float d) {
    asm volatile("st.shared.v4.f32 [%0],{%1,%2,%3,%4};" :: "r"(addr), "f"(a), "f"(b), "f"(c), "f"(d));
}
__device__ __forceinline__ void sts2(u32 addr, float a, float b) {
    asm volatile("st.shared.v2.f32 [%0],{%1,%2};" :: "r"(addr), "f"(a), "f"(b));
}
__device__ __forceinline__ u32 s2u(const void* p) {
    u32 a; asm("{.reg .u64 t; cvta.to.shared.u64 t,%1; cvt.u32.u64 %0,t;}" : "=r"(a) : "l"(p)); return a;
}
__device__ __forceinline__ void cpa16(u32 dst, const void* src, int bytes) {
    asm volatile("cp.async.cg.shared.global [%0],[%1],16,%2;" :: "r"(dst), "l"(src), "r"(bytes));
}
__device__ __forceinline__ void cpcommit() { asm volatile("cp.async.commit_group;"); }
__device__ __forceinline__ void cpwait0()  { asm volatile("cp.async.wait_group 0;"); }

// ---------------------------------------------------------------------------
// Stage A: per-ring DFT GEMM  C[m, bc] = sum_p basis[p,m] * x[bc,p]
// grid = (16 bc-tiles, 192 rings, 3 m-tiles of 64), block = 256.
// smem: CS[buf][16p][64m](cos,sin)  XS[buf][16p][66bc](x,x)
// ---------------------------------------------------------------------------
extern "C" __global__ void __launch_bounds__(256)
sht_stageA(const float* __restrict__ x,
           const float* __restrict__ cosb,
           const float* __restrict__ sinb)
{
    __shared__ __align__(16) unsigned char sm[2 * 16 * 512 + 2 * 16 * 528];
    const int t   = threadIdx.x;
    const int bc0 = blockIdx.x * 64;
    const int k   = blockIdx.y;
    const int m0  = blockIdx.z * 64;

    int nlon, slon, mmax;
    if (k < 96) { nlon = 24 + 4 * k; slon = 2 * k * k + 22 * k; mmax = 12 + 2 * k; }
    else { int q = 192 - k; nlon = 20 + 4 * q; slon = NGRID - (2 * q * q + 22 * q); mmax = 10 + 2 * q; }
    if (mmax > MDIM - 1) mmax = MDIM - 1;
    if (m0 > mmax) return;                 // inactive m-tile: never read downstream
    const int ntiles = (nlon + 15) >> 4;

    const u32 sb = s2u(sm);
    const u32 CS = sb;                     // buf stride 8192, row 512 B
    const u32 XS = sb + 16384;             // buf stride 8448, row 528 B

    const int tm = t >> 4, tb = t & 15;    // compute roles: 4 m, 4 bc each
    const int ppb = t >> 4, mq = (t & 15) * 4;   // basis staging
    const int bcr = t >> 2, pq = (t & 3) * 4;    // x staging

    const float* xrow  = x + (size_t)(bc0 + bcr) * NGRID + slon;
    const float* cbase = cosb + ((size_t)k * PMAX) * MDIM + m0 + mq;
    const float* sbase = sinb + ((size_t)k * PMAX) * MDIM + m0 + mq;

    u64 acc[4][4];
#pragma unroll
    for (int j = 0; j < 4; j++)
#pragma unroll
        for (int i = 0; i < 4; i++) acc[j][i] = 0ull;

    float4 c4, s4, xv;
    auto prefetch = [&](int p0) {
        int p = p0 + ppb;
        if (p < PMAX) {
            c4 = *(const float4*)(cbase + (size_t)p * MDIM);
            s4 = *(const float4*)(sbase + (size_t)p * MDIM);
        } else { c4 = make_float4(0, 0, 0, 0); s4 = c4; }
        int px = p0 + pq;                    // nlon % 4 == 0 -> full vec or none
        if (px < nlon) xv = *(const float4*)(xrow + px);
        else xv = make_float4(0, 0, 0, 0);
    };
    auto store_tile = [&](int buf) {
        u32 cs = CS + buf * 8192 + ppb * 512 + mq * 8;
        sts4(cs,      c4.x, s4.x, c4.y, s4.y);
        sts4(cs + 16, c4.z, s4.z, c4.w, s4.w);
        u32 xs = XS + buf * 8448 + pq * 528 + bcr * 8;
        sts2(xs,        xv.x, xv.x);
        sts2(xs + 528,  xv.y, xv.y);
        sts2(xs + 1056, xv.z, xv.z);
        sts2(xs + 1584, xv.w, xv.w);
    };
    auto compute = [&](int buf) {
        u32 cs = CS + buf * 8192 + tm * 32;
        u32 xs = XS + buf * 8448 + tb * 32;
#pragma unroll
        for (int pp = 0; pp < 16; ++pp) {
            u64 b[4], v[4];
            lds2(b[0], b[1], cs + pp * 512);
            lds2(b[2], b[3], cs + pp * 512 + 16);
            lds2(v[0], v[1], xs + pp * 528);
            lds2(v[2], v[3], xs + pp * 528 + 16);
#pragma unroll
            for (int j = 0; j < 4; j++)
#pragma unroll
                for (int i = 0; i < 4; i++)
                    acc[j][i] = ffma2(b[j], v[i], acc[j][i]);
        }
    };

    prefetch(0);
    store_tile(0);
    __syncthreads();
    for (int ti = 0; ti < ntiles; ++ti) {
        bool nx = (ti + 1) < ntiles;
        if (nx) prefetch((ti + 1) << 4);
        compute(ti & 1);
        __syncthreads();
        if (nx) store_tile((ti + 1) & 1);
        __syncthreads();
    }

    const u64 tp2 = pk2(TWO_PI_F, TWO_PI_F);
#pragma unroll
    for (int j = 0; j < 4; j++) {
        size_t base = (((size_t)(m0 + tm * 4 + j)) * KR + k) * BCN + bc0 + tb * 4;
        u64* o = (u64*)g_ri + base;
        ulonglong2 w0, w1;
        w0.x = fmul2(acc[j][0], tp2); w0.y = fmul2(acc[j][1], tp2);
        w1.x = fmul2(acc[j][2], tp2); w1.y = fmul2(acc[j][3], tp2);
        *(ulonglong2*)o       = w0;
        *(ulonglong2*)(o + 2) = w1;
    }
}

// ---------------------------------------------------------------------------
// Stage B: per-m GEMM over active latitude band
//   out[bc,l,m] = sum_{k in [klo,khi]} A[m,k,bc] * W[m,l,k]
// grid = (16 bc-tiles, 3 l-tiles, 192 m), block = 256.
// smem: AS[buf][16k][64bc](re,im)  WS[buf][16k][66l](w,w)
// ---------------------------------------------------------------------------
extern "C" __global__ void __launch_bounds__(256)
sht_stageB(const float* __restrict__ weight, u64* __restrict__ out)
{
    __shared__ __align__(16) unsigned char sm[2 * 16 * 512 + 2 * 16 * 528];
    const int t   = threadIdx.x;
    const int bc0 = blockIdx.x * 64;
    const int l0  = blockIdx.y * 64;
    const int m   = blockIdx.z;
    const int tl = t >> 4, tb = t & 15;

    if (l0 + 63 < m) {                      // entire tile strictly below diagonal
#pragma unroll
        for (int j = 0; j < 4; j++)
#pragma unroll
            for (int i = 0; i < 4; i++)
                out[(((size_t)(bc0 + tb * 4 + i)) * MDIM + l0 + tl * 4 + j) * MDIM + m] = 0ull;
        return;
    }

    const int klo = (m <= 12) ? 0 : ((m - 11) >> 1);
    int khi = (394 - m) >> 1; if (khi > KR - 1) khi = KR - 1;
    const int kb0 = klo & ~15;
    const int nkt = ((khi - kb0) >> 4) + 1;

    const u32 sb = s2u(sm);
    const u32 AS = sb;                      // buf stride 8192, row 512 B
    const u32 WS = sb + 16384;              // buf stride 8448, row 528 B

    const int ka = t >> 5, bq = (t & 31) * 2;     // A staging (2 cp.async each)
    const int lr = t >> 2, kq = (t & 3) * 4;      // W staging

    const float* wrow  = weight + ((size_t)m * MDIM + l0 + lr) * KR;
    const u64*   abase = (const u64*)g_ri + ((size_t)m * KR) * BCN + bc0;

    u64 acc[4][4];
#pragma unroll
    for (int j = 0; j < 4; j++)
#pragma unroll
        for (int i = 0; i < 4; i++) acc[j][i] = 0ull;

    float4 w4;
    auto cpa_tile = [&](int buf, int kb) {
#pragma unroll
        for (int r = 0; r < 2; r++) {
            int kk = ka + r * 8;
            int kg = kb + kk;
            int kgc = kg > KR - 1 ? KR - 1 : kg;
            const u64* src = abase + (size_t)kgc * BCN + bq;
            int bytes = (kg >= klo && kg <= khi) ? 16 : 0;   // zero-fill outside band
            cpa16(AS + buf * 8192 + kk * 512 + bq * 8, src, bytes);
        }
        cpcommit();
    };
    auto ldW = [&](int kb) { w4 = *(const float4*)(wrow + kb + kq); };
    auto stW = [&](int buf) {
        u32 ws = WS + buf * 8448 + kq * 528 + lr * 8;
        sts2(ws,        w4.x, w4.x);
        sts2(ws + 528,  w4.y, w4.y);
        sts2(ws + 1056, w4.z, w4.z);
        sts2(ws + 1584, w4.w, w4.w);
    };
    auto compute = [&](int buf) {
        u32 as = AS + buf * 8192 + tb * 32;
        u32 ws = WS + buf * 8448 + tl * 32;
#pragma unroll
        for (int kk = 0; kk < 16; ++kk) {
            u64 a[4], w[4];
            lds2(a[0], a[1], as + kk * 512);
            lds2(a[2], a[3], as + kk * 512 + 16);
            lds2(w[0], w[1], ws + kk * 528);
            lds2(w[2], w[3], ws + kk * 528 + 16);
#pragma unroll
            for (int j = 0; j < 4; j++)
#pragma unroll
                for (int i = 0; i < 4; i++)
                    acc[j][i] = ffma2(a[i], w[j], acc[j][i]);
        }
    };

    cpa_tile(0, kb0);
    ldW(kb0);
    stW(0);
    cpwait0();
    __syncthreads();
    for (int ti = 0; ti < nkt; ++ti) {
        int kb = kb0 + ((ti + 1) << 4);
        bool nx = (ti + 1) < nkt;
        if (nx) { cpa_tile((ti + 1) & 1, kb); ldW(kb); }
        compute(ti & 1);
        __syncthreads();
        if (nx) { stW((ti + 1) & 1); cpwait0(); }
        __syncthreads();
    }

#pragma unroll
    for (int j = 0; j < 4; j++)
#pragma unroll
        for (int i = 0; i < 4; i++)
            out[(((size_t)(bc0 + tb * 4 + i)) * MDIM + l0 + tl * 4 + j) * MDIM + m] = acc[j][i];
}

// ---------------------------------------------------------------------------

extern "C" void kernel_launch(void* const* d_in, const int* in_sizes, int n_in,
                              void* d_out, int out_size)
{
    (void)in_sizes; (void)n_in; (void)out_size;
    const float* x      = (const float*)d_in[0];
    const float* weight = (const float*)d_in[1];
    const float* cosb   = (const float*)d_in[2];
    const float* sinb   = (const float*)d_in[3];

    dim3 gA(16, 192, 3);
    sht_stageA<<<gA, 256>>>(x, cosb, sinb);

    dim3 gB(16, 3, 192);
    sht_stageB<<<gB, 256>>>(weight, (u64*)d_out);
}

// round 3
// speedup vs baseline: 2.9031x; 1.8297x over previous
#include <cuda_runtime.h>

#define NGRID   41088
#define PMAX    404
#define MDIM    192
#define KR      192
#define BCN     1024
#define TWO_PI_F 6.28318530717958647692f

typedef unsigned long long u64;
typedef unsigned int u32;

// Stage-A output: (re,im) pairs, layout [m][k][bc]
__device__ u64 g_ri[(size_t)MDIM * KR * BCN];
// Stage-B staging: (re,im) pairs, layout [m][l][bc]
__device__ u64 g_st[(size_t)MDIM * MDIM * BCN];

__device__ __forceinline__ u64 ffma2(u64 a, u64 b, u64 c) {
    u64 d; asm("fma.rn.f32x2 %0,%1,%2,%3;" : "=l"(d) : "l"(a), "l"(b), "l"(c)); return d;
}
__device__ __forceinline__ u64 fmul2(u64 a, u64 b) {
    u64 d; asm("mul.rn.f32x2 %0,%1,%2;" : "=l"(d) : "l"(a), "l"(b)); return d;
}
__device__ __forceinline__ u64 pk2(float lo, float hi) {
    u64 r; asm("mov.b64 %0,{%1,%2};" : "=l"(r) : "f"(lo), "f"(hi)); return r;
}
__device__ __forceinline__ void lds2(u64& a, u64& b, u32 addr) {
    asm volatile("ld.shared.v2.u64 {%0,%1},[%2];" : "=l"(a), "=l"(b) : "r"(addr));
}
__device__ __forceinline__ float4 lds4f(u32 addr) {
    float4 v;
    asm volatile("ld.shared.v4.f32 {%0,%1,%2,%3},[%4];"
                 : "=f"(v.x), "=f"(v.y), "=f"(v.z), "=f"(v.w) : "r"(addr));
    return v;
}
__device__ __forceinline__ void sts4(u32 addr, float a, float b, float c, float d) {
    asm volatile("st.shared.v4.f32 [%0],{%1,%2,%3,%4};" :: "r"(addr), "f"(a), "f"(b), "f"(c), "f"(d));
}
__device__ __forceinline__ void sts1(u32 addr, float a) {
    asm volatile("st.shared.f32 [%0],%1;" :: "r"(addr), "f"(a));
}
__device__ __forceinline__ u32 s2u(const void* p) {
    u32 a; asm("{.reg .u64 t; cvta.to.shared.u64 t,%1; cvt.u32.u64 %0,t;}" : "=r"(a) : "l"(p)); return a;
}
__device__ __forceinline__ void cpa16(u32 dst, const void* src, int bytes) {
    asm volatile("cp.async.cg.shared.global [%0],[%1],16,%2;" :: "r"(dst), "l"(src), "r"(bytes));
}
__device__ __forceinline__ void cpcommit() { asm volatile("cp.async.commit_group;"); }
__device__ __forceinline__ void cpwait0()  { asm volatile("cp.async.wait_group 0;"); }

// ---------------------------------------------------------------------------
// Stage A: per-ring DFT  acc[m,bc] = sum_p (cos,sin)[p,m] * x[bc,p]
// grid = (8 bc-tiles of 128, 192 rings, 3 m-tiles of 64), block = 256.
// smem: CS[buf][16p][64 m-pairs]   XS[buf][16p][128 bc scalars]
// thread tile: 4 m-pairs x 8 bc  (32 FFMA2 per p-step)
// ---------------------------------------------------------------------------
extern "C" __global__ void __launch_bounds__(256, 2)
sht_stageA(const float* __restrict__ x,
           const float* __restrict__ cosb,
           const float* __restrict__ sinb)
{
    __shared__ __align__(16) unsigned char sm[2 * 16 * 512 + 2 * 16 * 528];
    const int t   = threadIdx.x;
    const int bc0 = blockIdx.x * 128;
    const int k   = blockIdx.y;
    const int m0  = blockIdx.z * 64;

    int nlon, slon, mmax;
    if (k < 96) { nlon = 24 + 4 * k; slon = 2 * k * k + 22 * k; mmax = 12 + 2 * k; }
    else { int q = 192 - k; nlon = 20 + 4 * q; slon = NGRID - (2 * q * q + 22 * q); mmax = 10 + 2 * q; }
    if (mmax > MDIM - 1) mmax = MDIM - 1;
    if (m0 > mmax) return;                 // inactive m-tile: never read downstream
    const int ntiles = (nlon + 15) >> 4;

    const u32 sb = s2u(sm);
    const u32 CS = sb;                     // buf stride 8192, row 512 B
    const u32 XS = sb + 16384;             // buf stride 8448, row 528 B

    const int tm = t >> 4, tb = t & 15;          // compute: 4 m-pairs, 8 bc
    const int ppb = t >> 4, mq = (t & 15) * 4;   // basis staging
    const int bcr = t >> 1, pq8 = (t & 1) * 8;   // x staging: 2 float4 each

    const float* xrow  = x + (size_t)(bc0 + bcr) * NGRID + slon;
    const float* cbase = cosb + ((size_t)k * PMAX) * MDIM + m0 + mq;
    const float* sbase = sinb + ((size_t)k * PMAX) * MDIM + m0 + mq;

    u64 acc[4][8];
#pragma unroll
    for (int j = 0; j < 4; j++)
#pragma unroll
        for (int i = 0; i < 8; i++) acc[j][i] = 0ull;

    float4 c4, s4, xv0, xv1;
    auto prefetch = [&](int p0) {
        int p = p0 + ppb;
        if (p < PMAX) {                    // basis is zero for p in [nlon, PMAX)
            c4 = *(const float4*)(cbase + (size_t)p * MDIM);
            s4 = *(const float4*)(sbase + (size_t)p * MDIM);
        } else { c4 = make_float4(0, 0, 0, 0); s4 = c4; }
        int px = p0 + pq8;
        xv0 = (px     < nlon) ? *(const float4*)(xrow + px)     : make_float4(0, 0, 0, 0);
        xv1 = (px + 4 < nlon) ? *(const float4*)(xrow + px + 4) : make_float4(0, 0, 0, 0);
    };
    auto store_tile = [&](int buf) {
        u32 cs = CS + buf * 8192 + ppb * 512 + mq * 8;
        sts4(cs,      c4.x, s4.x, c4.y, s4.y);
        sts4(cs + 16, c4.z, s4.z, c4.w, s4.w);
        u32 xs = XS + buf * 8448 + pq8 * 528 + bcr * 4;
        sts1(xs,            xv0.x); sts1(xs + 528,      xv0.y);
        sts1(xs + 2 * 528,  xv0.z); sts1(xs + 3 * 528,  xv0.w);
        sts1(xs + 4 * 528,  xv1.x); sts1(xs + 5 * 528,  xv1.y);
        sts1(xs + 6 * 528,  xv1.z); sts1(xs + 7 * 528,  xv1.w);
    };
    auto compute = [&](int buf) {
        u32 cs = CS + buf * 8192 + tm * 32;
        u32 xs = XS + buf * 8448 + tb * 32;
#pragma unroll
        for (int pp = 0; pp < 16; ++pp) {
            u64 b[4];
            lds2(b[0], b[1], cs + pp * 512);
            lds2(b[2], b[3], cs + pp * 512 + 16);
            float4 v0 = lds4f(xs + pp * 528);
            float4 v1 = lds4f(xs + pp * 528 + 16);
            const float vs[8] = {v0.x, v0.y, v0.z, v0.w, v1.x, v1.y, v1.z, v1.w};
#pragma unroll
            for (int i = 0; i < 8; i++) {
                u64 vv = pk2(vs[i], vs[i]);
#pragma unroll
                for (int j = 0; j < 4; j++)
                    acc[j][i] = ffma2(b[j], vv, acc[j][i]);
            }
        }
    };

    prefetch(0);
    store_tile(0);
    __syncthreads();
    for (int ti = 0; ti < ntiles; ++ti) {
        bool nx = (ti + 1) < ntiles;
        if (nx) prefetch((ti + 1) << 4);
        compute(ti & 1);
        __syncthreads();
        if (nx) store_tile((ti + 1) & 1);
        __syncthreads();
    }

    const u64 tp2 = pk2(TWO_PI_F, TWO_PI_F);
#pragma unroll
    for (int j = 0; j < 4; j++) {
        u64* o = g_ri + (((size_t)(m0 + tm * 4 + j)) * KR + k) * BCN + bc0 + tb * 8;
#pragma unroll
        for (int i = 0; i < 4; i++) {
            ulonglong2 w;
            w.x = fmul2(acc[j][2 * i], tp2);
            w.y = fmul2(acc[j][2 * i + 1], tp2);
            *(ulonglong2*)(o + 2 * i) = w;
        }
    }
}

// ---------------------------------------------------------------------------
// Stage B: per-m GEMM over active latitude band
//   st[m,l,bc] = sum_{k in [klo,khi]} A[m,k,bc] * W[m,l,k]
// grid = (16 bc-tiles of 64, 3 l-tiles of 64, 192 m), block = 128.
// thread tile: 4 bc (contiguous) x 8 l. Sub-diagonal tiles skipped entirely.
// ---------------------------------------------------------------------------
extern "C" __global__ void __launch_bounds__(128, 4)
sht_stageB(const float* __restrict__ weight)
{
    __shared__ __align__(16) unsigned char sm[2 * 16 * 512 + 2 * 16 * 272];
    const int t   = threadIdx.x;
    const int bc0 = blockIdx.x * 64;
    const int l0  = blockIdx.y * 64;
    const int m   = blockIdx.z;
    if (l0 + 63 < m) return;               // zero triangle: handled by transpose

    const int tb = t & 15, tl = t >> 4;     // 4 bc, 8 l per thread

    const int klo = (m <= 12) ? 0 : ((m - 11) >> 1);
    int khi = (394 - m) >> 1; if (khi > KR - 1) khi = KR - 1;
    const int kb0 = klo & ~15;
    const int nkt = ((khi - kb0) >> 4) + 1;

    const u32 sb = s2u(sm);
    const u32 AS = sb;                      // buf stride 8192, row 512 B
    const u32 WS = sb + 16384;              // buf stride 4352, row 272 B

    const int lr = t >> 1, kq = (t & 1) * 8;      // W staging: 2 float4 each

    const float* wrow  = weight + ((size_t)m * MDIM + l0 + lr) * KR;
    const u64*   abase = g_ri + ((size_t)m * KR) * BCN + bc0;

    u64 acc[8][4];
#pragma unroll
    for (int j = 0; j < 8; j++)
#pragma unroll
        for (int i = 0; i < 4; i++) acc[j][i] = 0ull;

    float4 w40, w41;
    auto cpa_tile = [&](int buf, int kb) {
#pragma unroll
        for (int c = 0; c < 4; c++) {
            int chunk = t * 4 + c;          // 0..511
            int kk = chunk >> 5, col = chunk & 31;
            int kg = kb + kk;
            int kgc = kg > KR - 1 ? KR - 1 : kg;
            const u64* src = abase + (size_t)kgc * BCN + col * 2;
            int bytes = (kg >= klo && kg <= khi) ? 16 : 0;   // zero-fill outside band
            cpa16(AS + buf * 8192 + kk * 512 + col * 16, src, bytes);
        }
        cpcommit();
    };
    auto ldW = [&](int kb) {
        w40 = *(const float4*)(wrow + kb + kq);
        w41 = *(const float4*)(wrow + kb + kq + 4);
    };
    auto stW = [&](int buf) {
        u32 ws = WS + buf * 4352 + kq * 272 + lr * 4;
        sts1(ws,           w40.x); sts1(ws + 272,     w40.y);
        sts1(ws + 2 * 272, w40.z); sts1(ws + 3 * 272, w40.w);
        sts1(ws + 4 * 272, w41.x); sts1(ws + 5 * 272, w41.y);
        sts1(ws + 6 * 272, w41.z); sts1(ws + 7 * 272, w41.w);
    };
    auto compute = [&](int buf) {
        u32 as = AS + buf * 8192 + tb * 32;
        u32 ws = WS + buf * 4352 + tl * 32;
#pragma unroll
        for (int kk = 0; kk < 16; ++kk) {
            u64 a[4];
            lds2(a[0], a[1], as + kk * 512);
            lds2(a[2], a[3], as + kk * 512 + 16);
            float4 f0 = lds4f(ws + kk * 272);
            float4 f1 = lds4f(ws + kk * 272 + 16);
            const float fw[8] = {f0.x, f0.y, f0.z, f0.w, f1.x, f1.y, f1.z, f1.w};
#pragma unroll
            for (int j = 0; j < 8; j++) {
                u64 ww = pk2(fw[j], fw[j]);
#pragma unroll
                for (int i = 0; i < 4; i++)
                    acc[j][i] = ffma2(a[i], ww, acc[j][i]);
            }
        }
    };

    cpa_tile(0, kb0);
    ldW(kb0);
    stW(0);
    cpwait0();
    __syncthreads();
    for (int ti = 0; ti < nkt; ++ti) {
        int kb = kb0 + ((ti + 1) << 4);
        bool nx = (ti + 1) < nkt;
        if (nx) { cpa_tile((ti + 1) & 1, kb); ldW(kb); }
        compute(ti & 1);
        __syncthreads();
        if (nx) { stW((ti + 1) & 1); cpwait0(); }
        __syncthreads();
    }

    // coalesced staging writes: [m][l][bc], bc contiguous
#pragma unroll
    for (int j = 0; j < 8; j++) {
        u64* o = g_st + (((size_t)m * MDIM) + l0 + tl * 8 + j) * BCN + bc0 + tb * 4;
        ulonglong2 w0, w1;
        w0.x = acc[j][0]; w0.y = acc[j][1];
        w1.x = acc[j][2]; w1.y = acc[j][3];
        *(ulonglong2*)o       = w0;
        *(ulonglong2*)(o + 2) = w1;
    }
}

// ---------------------------------------------------------------------------
// Transpose: out[bc][l][m] <- g_st[m][l][bc]; zero for l < m.
// grid = (16 bc-tiles of 64, 6 m-tiles of 32, 192 l), block = 256.
// ---------------------------------------------------------------------------
extern "C" __global__ void __launch_bounds__(256)
sht_transpose(u64* __restrict__ out)
{
    __shared__ u64 smt[32][65];
    const int t   = threadIdx.x;
    const int bc0 = blockIdx.x * 64;
    const int m0  = blockIdx.y * 32;
    const int l   = blockIdx.z;

    // load: rows = m (contig bc), with zero for l < m
    const int mr  = t >> 5;            // 0..7
    const int bcc = (t & 31) * 2;      // 0..62
#pragma unroll
    for (int r = 0; r < 4; ++r) {
        int ml = mr + r * 8;
        ulonglong2 v;
        if (l >= m0 + ml)
            v = *(const ulonglong2*)(g_st + (((size_t)(m0 + ml)) * MDIM + l) * BCN + bc0 + bcc);
        else
            v = make_ulonglong2(0ull, 0ull);
        smt[ml][bcc]     = v.x;
        smt[ml][bcc + 1] = v.y;
    }
    __syncthreads();

    // store: rows = bc (contig m)
    const int bcr = t >> 4;            // 0..15
    const int mc  = (t & 15) * 2;      // 0..30
#pragma unroll
    for (int r = 0; r < 4; ++r) {
        int bcl = bcr + r * 16;
        ulonglong2 v;
        v.x = smt[mc][bcl];
        v.y = smt[mc + 1][bcl];
        *(ulonglong2*)(out + (((size_t)(bc0 + bcl)) * MDIM + l) * MDIM + m0 + mc) = v;
    }
}

// ---------------------------------------------------------------------------

extern "C" void kernel_launch(void* const* d_in, const int* in_sizes, int n_in,
                              void* d_out, int out_size)
{
    (void)in_sizes; (void)n_in; (void)out_size;
    const float* x      = (const float*)d_in[0];
    const float* weight = (const float*)d_in[1];
    const float* cosb   = (const float*)d_in[2];
    const float* sinb   = (const float*)d_in[3];

    dim3 gA(8, 192, 3);
    sht_stageA<<<gA, 256>>>(x, cosb, sinb);

    dim3 gB(16, 3, 192);
    sht_stageB<<<gB, 128>>>(weight);

    dim3 gT(16, 6, 192);
    sht_transpose<<<gT, 256>>>((u64*)d_out);
}

// round 4
// speedup vs baseline: 3.7716x; 1.2992x over previous
#include <cuda_runtime.h>

#define NGRID   41088
#define PMAX    404
#define MDIM    192
#define KR      192
#define BCN     1024
#define TWO_PI_F 6.28318530717958647692f

typedef unsigned long long u64;
typedef unsigned int u32;

// Stage-A output: (re,im) pairs, layout [m][k][bc]
__device__ u64 g_ri[(size_t)MDIM * KR * BCN];
// Stage-B staging: (re,im) pairs, layout [m][l][bc]
__device__ u64 g_st[(size_t)MDIM * MDIM * BCN];

__device__ __forceinline__ u64 ffma2(u64 a, u64 b, u64 c) {
    u64 d; asm("fma.rn.f32x2 %0,%1,%2,%3;" : "=l"(d) : "l"(a), "l"(b), "l"(c)); return d;
}
__device__ __forceinline__ u64 fmul2(u64 a, u64 b) {
    u64 d; asm("mul.rn.f32x2 %0,%1,%2;" : "=l"(d) : "l"(a), "l"(b)); return d;
}
__device__ __forceinline__ u64 pk2(float lo, float hi) {
    u64 r; asm("mov.b64 %0,{%1,%2};" : "=l"(r) : "f"(lo), "f"(hi)); return r;
}
__device__ __forceinline__ void lds2(u64& a, u64& b, u32 addr) {
    asm volatile("ld.shared.v2.u64 {%0,%1},[%2];" : "=l"(a), "=l"(b) : "r"(addr));
}
__device__ __forceinline__ u64 ldsu64(u32 addr) {
    u64 v; asm volatile("ld.shared.u64 %0,[%1];" : "=l"(v) : "r"(addr)); return v;
}
__device__ __forceinline__ float4 lds4f(u32 addr) {
    float4 v;
    asm volatile("ld.shared.v4.f32 {%0,%1,%2,%3},[%4];"
                 : "=f"(v.x), "=f"(v.y), "=f"(v.z), "=f"(v.w) : "r"(addr));
    return v;
}
__device__ __forceinline__ void sts4(u32 addr, float a, float b, float c, float d) {
    asm volatile("st.shared.v4.f32 [%0],{%1,%2,%3,%4};" :: "r"(addr), "f"(a), "f"(b), "f"(c), "f"(d));
}
__device__ __forceinline__ void sts2(u32 addr, float a, float b) {
    asm volatile("st.shared.v2.f32 [%0],{%1,%2};" :: "r"(addr), "f"(a), "f"(b));
}
__device__ __forceinline__ void sts1(u32 addr, float a) {
    asm volatile("st.shared.f32 [%0],%1;" :: "r"(addr), "f"(a));
}
__device__ __forceinline__ u32 s2u(const void* p) {
    u32 a; asm("{.reg .u64 t; cvta.to.shared.u64 t,%1; cvt.u32.u64 %0,t;}" : "=r"(a) : "l"(p)); return a;
}
__device__ __forceinline__ void cpa16(u32 dst, const void* src, int bytes) {
    asm volatile("cp.async.cg.shared.global [%0],[%1],16,%2;" :: "r"(dst), "l"(src), "r"(bytes));
}
__device__ __forceinline__ void cpcommit() { asm volatile("cp.async.commit_group;"); }
__device__ __forceinline__ void cpwait0()  { asm volatile("cp.async.wait_group 0;"); }

// ---------------------------------------------------------------------------
// Stage A: folded per-ring DFT.
//   re[m,bc] = sum_{q=0..nlon/2} c[q,m] * xplus[bc,q]
//   im[m,bc] = sum_{q=0..nlon/2} s[q,m] * xminus[bc,q]
// xplus/xminus = x[q] +/- x[nlon-q]  (edges q=0, q=nlon/2 special-cased).
// grid = (8 bc-tiles of 128, 192 rings, 3 m-tiles of 64), block = 256.
// smem: CS[buf][16q][64 (c,s) pairs]   XS[buf][16q][128 (x+,x-) pairs]
// thread tile: 4 m x 8 bc, conflict-free scalar u64 loads for x-pairs.
// ---------------------------------------------------------------------------
extern "C" __global__ void __launch_bounds__(256, 2)
sht_stageA(const float* __restrict__ x,
           const float* __restrict__ cosb,
           const float* __restrict__ sinb)
{
    __shared__ __align__(16) unsigned char sm[2 * 16 * 512 + 2 * 16 * 1024]; // 49152
    const int t   = threadIdx.x;
    const int bc0 = blockIdx.x * 128;
    const int k   = blockIdx.y;
    const int m0  = blockIdx.z * 64;

    int nlon, slon, mmax;
    if (k < 96) { nlon = 24 + 4 * k; slon = 2 * k * k + 22 * k; mmax = 12 + 2 * k; }
    else { int q = 192 - k; nlon = 20 + 4 * q; slon = NGRID - (2 * q * q + 22 * q); mmax = 10 + 2 * q; }
    if (mmax > MDIM - 1) mmax = MDIM - 1;
    if (m0 > mmax) return;                  // inactive m-tile: never read downstream
    const int half   = nlon >> 1;
    const int ntiles = (half + 16) >> 4;    // ceil((half+1)/16)

    const u32 sb = s2u(sm);
    const u32 CS = sb;                      // buf stride 8192, row 512 B
    const u32 XS = sb + 16384;              // buf stride 16384, row 1024 B

    const int tm = t >> 4, tb = t & 15;          // compute: 4 m, 8 bc
    const int ppb = t >> 4, mq = (t & 15) * 4;   // basis staging: 1 q-row, 4 m
    const int bcr = t >> 1, pq = (t & 1) * 8;    // x staging: 1 bc-row, 8 q

    const float* xrow  = x + (size_t)(bc0 + bcr) * NGRID + slon;
    const float* cbase = cosb + ((size_t)k * PMAX) * MDIM + m0 + mq;
    const float* sbase = sinb + ((size_t)k * PMAX) * MDIM + m0 + mq;

    u64 acc[4][8];
#pragma unroll
    for (int j = 0; j < 4; j++)
#pragma unroll
        for (int i = 0; i < 8; i++) acc[j][i] = 0ull;

    float4 c4, s4, fw0, fw1, bw0, bw1;
    float ps0, ps1;
    int p0s;
    const float4 z4 = make_float4(0.f, 0.f, 0.f, 0.f);

    auto prefetch = [&](int p0) {
        p0s = p0;
        int p = p0 + ppb;                   // p <= 207 < PMAX always: in-bounds
        c4 = *(const float4*)(cbase + (size_t)p * MDIM);
        s4 = *(const float4*)(sbase + (size_t)p * MDIM);
        int q0 = p0 + pq;
        if (q0 <= half) {
            fw0 = *(const float4*)(xrow + q0);
            bw0 = *(const float4*)(xrow + nlon - q0 - 4);
            ps0 = (q0 >= 1) ? xrow[nlon - q0] : 0.f;
        } else { fw0 = z4; bw0 = z4; ps0 = 0.f; }
        int q1 = q0 + 4;
        if (q1 <= half) {
            fw1 = *(const float4*)(xrow + q1);
            bw1 = *(const float4*)(xrow + nlon - q1 - 4);
            ps1 = xrow[nlon - q1];
        } else { fw1 = z4; bw1 = z4; ps1 = 0.f; }
    };

    auto fold_emit = [&](u32 a, float4 f, float4 b, float ps, int qv) {
        float fr[4] = {f.x, f.y, f.z, f.w};
        float pr[4] = {ps, b.w, b.z, b.y};
#pragma unroll
        for (int i = 0; i < 4; i++) {
            int q = qv + i;
            bool valid = q <= half;
            bool spec  = (q == 0) || (q == half);
            float pl = valid ? (spec ? fr[i] : fr[i] + pr[i]) : 0.f;
            float mi = (valid && !spec) ? fr[i] - pr[i] : 0.f;
            sts2(a + i * 1024, pl, mi);
        }
    };

    auto store_tile = [&](int buf) {
        u32 cs = CS + buf * 8192 + ppb * 512 + mq * 8;
        sts4(cs,      c4.x, s4.x, c4.y, s4.y);
        sts4(cs + 16, c4.z, s4.z, c4.w, s4.w);
        u32 xa = XS + buf * 16384 + pq * 1024 + bcr * 8;
        int q0 = p0s + pq;
        fold_emit(xa,        fw0, bw0, ps0, q0);
        fold_emit(xa + 4096, fw1, bw1, ps1, q0 + 4);
    };

    auto compute = [&](int buf) {
        u32 cs = CS + buf * 8192 + tm * 32;
        u32 xs = XS + buf * 16384 + tb * 8;
#pragma unroll
        for (int pp = 0; pp < 16; ++pp) {
            u64 b0, b1, b2, b3;
            lds2(b0, b1, cs + pp * 512);
            lds2(b2, b3, cs + pp * 512 + 16);
            u64 v[8];
#pragma unroll
            for (int i = 0; i < 8; i++) v[i] = ldsu64(xs + pp * 1024 + i * 128);
#pragma unroll
            for (int i = 0; i < 8; i++) {
                acc[0][i] = ffma2(b0, v[i], acc[0][i]);
                acc[1][i] = ffma2(b1, v[i], acc[1][i]);
                acc[2][i] = ffma2(b2, v[i], acc[2][i]);
                acc[3][i] = ffma2(b3, v[i], acc[3][i]);
            }
        }
    };

    prefetch(0);
    store_tile(0);
    __syncthreads();
    for (int ti = 0; ti < ntiles; ++ti) {
        bool nx = (ti + 1) < ntiles;
        if (nx) prefetch((ti + 1) << 4);
        compute(ti & 1);
        if (nx) store_tile((ti + 1) & 1);
        __syncthreads();
    }

    const u64 tp2 = pk2(TWO_PI_F, TWO_PI_F);
#pragma unroll
    for (int j = 0; j < 4; j++) {
        u64* o = g_ri + (((size_t)(m0 + tm * 4 + j)) * KR + k) * BCN + bc0 + tb;
#pragma unroll
        for (int i = 0; i < 8; i++)
            o[i * 16] = fmul2(acc[j][i], tp2);
    }
}

// ---------------------------------------------------------------------------
// Stage B: per-m GEMM over active latitude band
//   st[m,l,bc] = sum_{k in [klo,khi]} A[m,k,bc] * W[m,l,k]
// grid = (16 bc-tiles of 64, 3 l-tiles of 64, 192 m), block = 128.
// thread tile: 8 l x 4 bc (bc = tb + 16i, conflict-free u64 loads).
// ---------------------------------------------------------------------------
extern "C" __global__ void __launch_bounds__(128, 4)
sht_stageB(const float* __restrict__ weight)
{
    __shared__ __align__(16) unsigned char sm[2 * 16 * 512 + 2 * 16 * 272];
    const int t   = threadIdx.x;
    const int bc0 = blockIdx.x * 64;
    const int l0  = blockIdx.y * 64;
    const int m   = blockIdx.z;
    if (l0 + 63 < m) return;                // zero triangle: handled by transpose

    const int tb = t & 15, tl = t >> 4;     // 4 bc, 8 l per thread

    const int klo = (m <= 12) ? 0 : ((m - 11) >> 1);
    int khi = (394 - m) >> 1; if (khi > KR - 1) khi = KR - 1;
    const int kb0 = klo & ~15;
    const int nkt = ((khi - kb0) >> 4) + 1;

    const u32 sb = s2u(sm);
    const u32 AS = sb;                      // buf stride 8192, row 512 B
    const u32 WS = sb + 16384;              // buf stride 4352, row 272 B

    const int lr = t >> 1, kq = (t & 1) * 8;      // W staging: 2 float4 each

    const float* wrow  = weight + ((size_t)m * MDIM + l0 + lr) * KR;
    const u64*   abase = g_ri + ((size_t)m * KR) * BCN + bc0;

    u64 acc[8][4];
#pragma unroll
    for (int j = 0; j < 8; j++)
#pragma unroll
        for (int i = 0; i < 4; i++) acc[j][i] = 0ull;

    float4 w40, w41;
    auto cpa_tile = [&](int buf, int kb) {
#pragma unroll
        for (int c = 0; c < 4; c++) {
            int chunk = t * 4 + c;          // 0..511
            int kk = chunk >> 5, col = chunk & 31;
            int kg = kb + kk;
            int kgc = kg > KR - 1 ? KR - 1 : kg;
            const u64* src = abase + (size_t)kgc * BCN + col * 2;
            int bytes = (kg >= klo && kg <= khi) ? 16 : 0;   // zero-fill outside band
            cpa16(AS + buf * 8192 + kk * 512 + col * 16, src, bytes);
        }
        cpcommit();
    };
    auto ldW = [&](int kb) {
        w40 = *(const float4*)(wrow + kb + kq);
        w41 = *(const float4*)(wrow + kb + kq + 4);
    };
    auto stW = [&](int buf) {
        u32 ws = WS + buf * 4352 + kq * 272 + lr * 4;
        sts1(ws,           w40.x); sts1(ws + 272,     w40.y);
        sts1(ws + 2 * 272, w40.z); sts1(ws + 3 * 272, w40.w);
        sts1(ws + 4 * 272, w41.x); sts1(ws + 5 * 272, w41.y);
        sts1(ws + 6 * 272, w41.z); sts1(ws + 7 * 272, w41.w);
    };
    auto compute = [&](int buf) {
        u32 as_ = AS + buf * 8192 + tb * 8;
        u32 ws  = WS + buf * 4352 + tl * 32;
#pragma unroll
        for (int kk = 0; kk < 16; ++kk) {
            u64 a[4];
#pragma unroll
            for (int i = 0; i < 4; i++) a[i] = ldsu64(as_ + kk * 512 + i * 128);
            float4 f0 = lds4f(ws + kk * 272);
            float4 f1 = lds4f(ws + kk * 272 + 16);
            const float fw[8] = {f0.x, f0.y, f0.z, f0.w, f1.x, f1.y, f1.z, f1.w};
#pragma unroll
            for (int j = 0; j < 8; j++) {
                u64 ww = pk2(fw[j], fw[j]);
#pragma unroll
                for (int i = 0; i < 4; i++)
                    acc[j][i] = ffma2(a[i], ww, acc[j][i]);
            }
        }
    };

    cpa_tile(0, kb0);
    ldW(kb0);
    stW(0);
    cpwait0();
    __syncthreads();
    for (int ti = 0; ti < nkt; ++ti) {
        int kb = kb0 + ((ti + 1) << 4);
        bool nx = (ti + 1) < nkt;
        if (nx) { cpa_tile((ti + 1) & 1, kb); ldW(kb); }
        compute(ti & 1);
        if (nx) { stW((ti + 1) & 1); cpwait0(); }
        __syncthreads();
    }

    // coalesced staging writes: [m][l][bc], bc contiguous
#pragma unroll
    for (int j = 0; j < 8; j++) {
        u64* o = g_st + (((size_t)m * MDIM) + l0 + tl * 8 + j) * BCN + bc0 + tb;
#pragma unroll
        for (int i = 0; i < 4; i++)
            o[i * 16] = acc[j][i];
    }
}

// ---------------------------------------------------------------------------
// Transpose: out[bc][l][m] <- g_st[m][l][bc]; zero for l < m.
// grid = (16 bc-tiles of 64, 6 m-tiles of 32, 192 l), block = 256.
// ---------------------------------------------------------------------------
extern "C" __global__ void __launch_bounds__(256)
sht_transpose(u64* __restrict__ out)
{
    __shared__ u64 smt[32][65];
    const int t   = threadIdx.x;
    const int bc0 = blockIdx.x * 64;
    const int m0  = blockIdx.y * 32;
    const int l   = blockIdx.z;

    // load: rows = m (contig bc), with zero for l < m
    const int mr  = t >> 5;            // 0..7
    const int bcc = (t & 31) * 2;      // 0..62
#pragma unroll
    for (int r = 0; r < 4; ++r) {
        int ml = mr + r * 8;
        ulonglong2 v;
        if (l >= m0 + ml)
            v = *(const ulonglong2*)(g_st + (((size_t)(m0 + ml)) * MDIM + l) * BCN + bc0 + bcc);
        else
            v = make_ulonglong2(0ull, 0ull);
        smt[ml][bcc]     = v.x;
        smt[ml][bcc + 1] = v.y;
    }
    __syncthreads();

    // store: rows = bc (contig m)
    const int bcr = t >> 4;            // 0..15
    const int mc  = (t & 15) * 2;      // 0..30
#pragma unroll
    for (int r = 0; r < 4; ++r) {
        int bcl = bcr + r * 16;
        ulonglong2 v;
        v.x = smt[mc][bcl];
        v.y = smt[mc + 1][bcl];
        *(ulonglong2*)(out + (((size_t)(bc0 + bcl)) * MDIM + l) * MDIM + m0 + mc) = v;
    }
}

// ---------------------------------------------------------------------------

extern "C" void kernel_launch(void* const* d_in, const int* in_sizes, int n_in,
                              void* d_out, int out_size)
{
    (void)in_sizes; (void)n_in; (void)out_size;
    const float* x      = (const float*)d_in[0];
    const float* weight = (const float*)d_in[1];
    const float* cosb   = (const float*)d_in[2];
    const float* sinb   = (const float*)d_in[3];

    dim3 gA(8, 192, 3);
    sht_stageA<<<gA, 256>>>(x, cosb, sinb);

    dim3 gB(16, 3, 192);
    sht_stageB<<<gB, 128>>>(weight);

    dim3 gT(16, 6, 192);
    sht_transpose<<<gT, 256>>>((u64*)d_out);
}